// round 15
// baseline (speedup 1.0000x reference)
#include <cuda_runtime.h>
#include <cuda_fp16.h>
#include <math.h>
#include <stdint.h>

#define NB   8
#define NH   8
#define DD   64
#define CC   64
#define LL   1024
#define MM   1024
#define NCH  512
#define BHN  64
#define EPSF 1e-3f

// attn smem layout (byte offsets)
#define QSTR 136
#define KSTR 72
#define VSTR 72
#define OSTR 132
#define QH_B  0
#define KH0_B 17408
#define KH1_B 26624
#define VH0_B 35840
#define VH1_B 45056
#define SCL_B 54272
#define ATTN_SMEM_BYTES 54288
#define KVSTRB 144            // KSTR*2 bytes per smem row

// gram smem
#define GSTR 72

#define LOG2E  1.4426950408889634f
#define SHIFT2 5.770780163555854f

// ---------------- scratch ----------------
__device__ float g_gram[2 * 64 * 4096];
__device__ float g_rsum[2 * 64 * 64];
__device__ float g_bh_sum[BHN];
__device__ float g_bh_sq[BHN];
__device__ float g_ch_sum[NCH * 64];
__device__ float g_ch_sq[NCH * 64];
__device__ __half g_kh[64 * 64 * 1024];   // fp16 K, [bh][d][m]
__device__ __half g_vh[64 * 64 * 1024];   // fp16 V, [bh][c][m]

// ---------------- helpers ----------------
__device__ __forceinline__ void ldsm4(unsigned r[4], unsigned addr) {
    asm volatile("ldmatrix.sync.aligned.m8n8.x4.shared.b16 {%0,%1,%2,%3}, [%4];"
        : "=r"(r[0]), "=r"(r[1]), "=r"(r[2]), "=r"(r[3]) : "r"(addr));
}
__device__ __forceinline__ void ldsm4t(unsigned r[4], unsigned addr) {
    asm volatile("ldmatrix.sync.aligned.m8n8.x4.trans.shared.b16 {%0,%1,%2,%3}, [%4];"
        : "=r"(r[0]), "=r"(r[1]), "=r"(r[2]), "=r"(r[3]) : "r"(addr));
}
// NOTE: non-volatile — pure register op; lets ptxas interleave independent
// MMA chains with softmax math and LDSM issue. Data deps keep accumulation
// order bit-identical.
__device__ __forceinline__ void mma16816(float c[4], const unsigned a[4],
                                         unsigned b0, unsigned b1) {
    asm("mma.sync.aligned.m16n8k16.row.col.f32.f16.f16.f32 "
        "{%0,%1,%2,%3}, {%4,%5,%6,%7}, {%8,%9}, {%0,%1,%2,%3};"
        : "+f"(c[0]), "+f"(c[1]), "+f"(c[2]), "+f"(c[3])
        : "r"(a[0]), "r"(a[1]), "r"(a[2]), "r"(a[3]), "r"(b0), "r"(b1));
}
__device__ __forceinline__ void hstore2(__half* ph, int off, float x, float y) {
    __half2 H = __floats2half2_rn(x, y);
    *reinterpret_cast<__half2*>(ph + off) = H;
}
__device__ __forceinline__ unsigned hpack(float x, float y) {
    __half2 H = __floats2half2_rn(x, y);
    return *reinterpret_cast<unsigned*>(&H);
}
__device__ __forceinline__ void cpa16(uint32_t saddr, const void* gptr) {
    asm volatile("cp.async.cg.shared.global [%0], [%1], 16;"
                 :: "r"(saddr), "l"(gptr) : "memory");
}
#define CPA_COMMIT() asm volatile("cp.async.commit_group;" ::: "memory")
#define CPA_WAIT0()  asm volatile("cp.async.wait_group 0;" ::: "memory")

// =====================================================================
// Kernel 1: grid (64, 3).
//   y<2 : tensor-core Gram (Ghat = Xhi·Xhi^T + Xhi·(2Xlo)^T) + fp16 K export
//   y==2: V fp32->fp16 convert for bh = blockIdx.x (runs concurrently)
// =====================================================================
__global__ void __launch_bounds__(256) gram_tc(
    const float* __restrict__ Q, const float* __restrict__ K,
    const float* __restrict__ V)
{
    const int bh = blockIdx.x, qk = blockIdx.y;
    const int t = threadIdx.x;

    if (qk == 2) {   // ---- V convert slice: 16384 float4 for this bh ----
        int base = bh * 16384 + t;
#pragma unroll 8
        for (int i = 0; i < 64; i++) {
            int idx = base + i * 256;
            float4 v = ((const float4*)V)[idx];
            __half2 a = __floats2half2_rn(v.x, v.y);
            __half2 b = __floats2half2_rn(v.z, v.w);
            ((uint2*)g_vh)[idx] = make_uint2(*(unsigned*)&a, *(unsigned*)&b);
        }
        return;
    }

    __shared__ __align__(16) unsigned char gsm[34816];
    __half* XH  = (__half*)gsm;            // [64 l][GSTR] hi
    __half* XL2 = (__half*)(gsm + 9216);   // [64 l][GSTR] 2*lo
    float*  SX  = (float*)(gsm + 18432);   // [64 d][64 l] staging

    const float* X = (qk ? K : Q) + (size_t)bh * (DD * LL);
    const int lane = t & 31, w = t >> 5;
    const int wm = w >> 1, wn = w & 1;
    const uint32_t s0 = (uint32_t)__cvta_generic_to_shared(gsm);
    const int sd = t >> 4, smj = (t & 15) << 2;

#pragma unroll
    for (int kk = 0; kk < 4; kk++) {
        int d = sd + kk * 16;
        cpa16(s0 + 18432 + (d * 64 + smj) * 4, X + d * LL + smj);
    }
    CPA_COMMIT();

    const unsigned aoff = 2 * (((lane & 7) + ((lane & 16) >> 1)) * GSTR + (wm << 4) + (lane & 8));
    const unsigned boff = 2 * (((lane & 7) + (lane & 8)) * GSTR + ((lane & 16) >> 1) + wn * 32);

    float gc[4][4];
#pragma unroll
    for (int i = 0; i < 4; i++)
#pragma unroll
        for (int j = 0; j < 4; j++) gc[i][j] = 0.f;
    float rs[4] = {0.f, 0.f, 0.f, 0.f};

    for (int c = 0; c < 16; c++) {
        CPA_WAIT0();
        __syncthreads();
#pragma unroll
        for (int kk = 0; kk < 4; kk++) {
            int d = sd + kk * 16;
            float4 v = *(const float4*)(SX + d * 64 + smj);
            rs[kk] += v.x + v.y + v.z + v.w;
            if (qk) {   // export fp16 K (coalesced 8B per thread)
                __half2 h01 = __floats2half2_rn(v.x, v.y);
                __half2 h23 = __floats2half2_rn(v.z, v.w);
                uint2 pk = make_uint2(*(unsigned*)&h01, *(unsigned*)&h23);
                *(uint2*)(g_kh + ((((size_t)bh << 6) + d) << 10) + c * 64 + smj) = pk;
            }
            const float vv[4] = {v.x, v.y, v.z, v.w};
#pragma unroll
            for (int j = 0; j < 4; j++) {
                int jj = (j + (lane & 3)) & 3;
                float x = vv[jj];
                __half hi = __float2half_rn(x);
                XH [(smj + jj) * GSTR + d] = hi;
                XL2[(smj + jj) * GSTR + d] = __float2half_rn(2.0f * (x - __half2float(hi)));
            }
        }
        __syncthreads();
        if (c < 15) {
            int l1 = (c + 1) * 64;
#pragma unroll
            for (int kk = 0; kk < 4; kk++) {
                int d = sd + kk * 16;
                cpa16(s0 + 18432 + (d * 64 + smj) * 4, X + d * LL + l1 + smj);
            }
        }
        CPA_COMMIT();

#pragma unroll
        for (int kt = 0; kt < 4; kt++) {
            unsigned a[4];
            ldsm4t(a, s0 + aoff + kt * (16 * GSTR * 2));
#pragma unroll
            for (int ntp = 0; ntp < 2; ntp++) {
                unsigned bh4[4], bl4[4];
                unsigned ka = s0 + boff + kt * (16 * GSTR * 2) + ntp * 32;
                ldsm4t(bh4, ka);
                ldsm4t(bl4, ka + 9216);
                mma16816(gc[2 * ntp],     a, bh4[0], bh4[1]);
                mma16816(gc[2 * ntp],     a, bl4[0], bl4[1]);
                mma16816(gc[2 * ntp + 1], a, bh4[2], bh4[3]);
                mma16816(gc[2 * ntp + 1], a, bl4[2], bl4[3]);
            }
        }
    }

#pragma unroll
    for (int kk = 0; kk < 4; kk++) {
        float v = rs[kk];
        v += __shfl_xor_sync(0xffffffffu, v, 1);
        v += __shfl_xor_sync(0xffffffffu, v, 2);
        v += __shfl_xor_sync(0xffffffffu, v, 4);
        v += __shfl_xor_sync(0xffffffffu, v, 8);
        if ((lane & 15) == 0)
            g_rsum[(qk * 64 + bh) * 64 + sd + 16 * kk] = v;
    }

    float* gb = g_gram + (size_t)(qk * 64 + bh) * 4096;
    const int r = lane >> 2, cc = (lane & 3) << 1;
#pragma unroll
    for (int f = 0; f < 4; f++) {
        int m = wm * 16 + r;
        int n = wn * 32 + f * 8 + cc;
        gb[m * 64 + n]           = gc[f][0];
        gb[m * 64 + n + 1]       = gc[f][1];
        gb[(m + 8) * 64 + n]     = gc[f][2];
        gb[(m + 8) * 64 + n + 1] = gc[f][3];
    }
}

// =====================================================================
// Kernel 2: Frobenius dot + rowsum dot per (b,h).
// =====================================================================
__global__ void __launch_bounds__(256) frob_reduce()
{
    __shared__ float red[256];
    const int bh = blockIdx.x;
    const int t  = threadIdx.x;
    const float* gq = g_gram + (size_t)(0 * 64 + bh) * 4096;
    const float* gk = g_gram + (size_t)(1 * 64 + bh) * 4096;

    float acc = 0.f;
#pragma unroll
    for (int k = 0; k < 16; k++) {
        int p = t + k * 256;
        acc += gq[p] * gk[p];
    }
    red[t] = acc;
    __syncthreads();
    for (int s = 128; s > 0; s >>= 1) {
        if (t < s) red[t] += red[t + s];
        __syncthreads();
    }
    if (t == 0) g_bh_sq[bh] = red[0];
    __syncthreads();

    float rv = 0.f;
    if (t < 64) {
        rv = g_rsum[(0 * 64 + bh) * 64 + t] * g_rsum[(1 * 64 + bh) * 64 + t];
    }
    red[t] = rv;
    __syncthreads();
    for (int s = 128; s > 0; s >>= 1) {
        if (t < s) red[t] += red[t + s];
        __syncthreads();
    }
    if (t == 0) g_bh_sum[bh] = red[0];
}

// =====================================================================
// Kernel 3: fp16 flash attention, direct fp16 cp.async ping-pong.
// S = Qhi·Khi; P = exp2(s' - 4*log2e); O += Phi·Vhi. One sync per iter.
// grid (8 ltiles, 64 bh), 256 threads = 8 warps, BL=128, BM=64.
// =====================================================================
__global__ void __launch_bounds__(256, 2) attn_kernel(
    const float* __restrict__ Q, const float* __restrict__ gamma_sim,
    float* __restrict__ out)
{
    extern __shared__ __align__(16) unsigned char smraw[];
    __half* QH = (__half*)smraw;
    float* Os = (float*)smraw;   // epilogue reuse

    const int bh = blockIdx.y;
    const int l0 = blockIdx.x << 7;
    const int h  = bh & 7;
    const int b  = bh >> 3;
    const int t    = threadIdx.x;
    const int lane = t & 31;
    const int w    = t >> 5;

    const float*  Qb = Q + (size_t)bh * (DD * LL);
    const __half* Kb = g_kh + ((size_t)bh << 16);
    const __half* Vb = g_vh + ((size_t)bh << 16);

    const uint32_t s0 = (unsigned)__cvta_generic_to_shared(smraw);

    // cp.async chunk indices: 512 16B-chunks per tile (64 rows x 8)
    const int r0c = t >> 3,  c0c = (t & 7);
    const int r1c = r0c + 32;

    // ---- prologue: prefetch K/V tile 0 into buffer 0 ----
    cpa16(s0 + KH0_B + r0c * KVSTRB + c0c * 16, Kb + (r0c << 10) + c0c * 8);
    cpa16(s0 + KH0_B + r1c * KVSTRB + c0c * 16, Kb + (r1c << 10) + c0c * 8);
    cpa16(s0 + VH0_B + r0c * KVSTRB + c0c * 16, Vb + (r0c << 10) + c0c * 8);
    cpa16(s0 + VH0_B + r1c * KVSTRB + c0c * 16, Vb + (r1c << 10) + c0c * 8);
    CPA_COMMIT();

    // ---- per-head scale (folded log2e) from gram stats ----
    if (t == 0) {
        float s = 0.f, q = 0.f;
#pragma unroll
        for (int bb = 0; bb < NB; bb++) {
            s += g_bh_sum[bb * NH + h];
            q += g_bh_sq[bb * NH + h];
        }
        const float cnt = (float)NB * (float)LL * (float)MM;
        float mean = s / cnt;
        float var  = q / cnt - mean * mean;
        *(float*)(smraw + SCL_B) = gamma_sim[h] * rsqrtf(var + EPSF) * LOG2E;
    }
    __syncthreads();
    const float sscale = *(const float*)(smraw + SCL_B);

    // ---- Q tile load+convert (pre-scaled) ----
#pragma unroll
    for (int kk = 0; kk < 8; kk++) {
        int f = t + kk * 256;
        int d = f >> 5, pos = (f & 31) << 2;
        float4 val = *(const float4*)(Qb + d * LL + l0 + pos);
        int off = d * QSTR + pos;
        hstore2(QH, off,     val.x * sscale, val.y * sscale);
        hstore2(QH, off + 2, val.z * sscale, val.w * sscale);
    }
    __syncthreads();

    const unsigned qoff = QH_B + 2 * (((lane & 7) + ((lane & 16) >> 1)) * QSTR + (w << 4) + (lane & 8));
    const unsigned koff = 2 * (((lane & 7) + (lane & 8)) * KSTR + ((lane & 16) >> 1));
    const unsigned voff = 2 * (((lane & 7) + ((lane & 16) >> 1)) * VSTR + (lane & 8));

    // ---- hoist loop-invariant Q A-fragments ----
    unsigned aH[4][4];
#pragma unroll
    for (int kt = 0; kt < 4; kt++)
        ldsm4t(aH[kt], s0 + qoff + kt * (16 * QSTR * 2));

    float oc[8][4];
#pragma unroll
    for (int i = 0; i < 8; i++)
#pragma unroll
        for (int j = 0; j < 4; j++) oc[i][j] = 0.f;
    float psum0 = 0.f, psum1 = 0.f;

    for (int it = 0; it < 16; it++) {
        CPA_WAIT0();          // tile it landed in buf (it&1)
        __syncthreads();      // all see it; prev MMA done with other buf

        // ---- prefetch tile it+1 into the other buffer ----
        if (it < 15) {
            const int m1 = (it + 1) << 6;
            const uint32_t kb = s0 + ((it & 1) ? KH0_B : KH1_B);
            const uint32_t vb = s0 + ((it & 1) ? VH0_B : VH1_B);
            cpa16(kb + r0c * KVSTRB + c0c * 16, Kb + (r0c << 10) + m1 + c0c * 8);
            cpa16(kb + r1c * KVSTRB + c0c * 16, Kb + (r1c << 10) + m1 + c0c * 8);
            cpa16(vb + r0c * KVSTRB + c0c * 16, Vb + (r0c << 10) + m1 + c0c * 8);
            cpa16(vb + r1c * KVSTRB + c0c * 16, Vb + (r1c << 10) + m1 + c0c * 8);
        }
        CPA_COMMIT();

        const uint32_t kcur = s0 + ((it & 1) ? KH1_B : KH0_B) + koff;
        const uint32_t vcur = s0 + ((it & 1) ? VH1_B : VH0_B) + voff;

        // ---- S = Qhi·Khi ----
        float sc[8][4];
#pragma unroll
        for (int i = 0; i < 8; i++)
#pragma unroll
            for (int j = 0; j < 4; j++) sc[i][j] = 0.f;

#pragma unroll
        for (int kt = 0; kt < 4; kt++) {
#pragma unroll
            for (int ntp = 0; ntp < 4; ntp++) {
                unsigned bHf[4];
                ldsm4t(bHf, kcur + kt * (16 * KSTR * 2) + ntp * 32);
                mma16816(sc[2 * ntp],     aH[kt], bHf[0], bHf[1]);
                mma16816(sc[2 * ntp + 1], aH[kt], bHf[2], bHf[3]);
            }
        }

        // ---- shifted exp2 softmax ----
#pragma unroll
        for (int nt = 0; nt < 8; nt++) {
            sc[nt][0] = exp2f(sc[nt][0] - SHIFT2);
            sc[nt][1] = exp2f(sc[nt][1] - SHIFT2);
            sc[nt][2] = exp2f(sc[nt][2] - SHIFT2);
            sc[nt][3] = exp2f(sc[nt][3] - SHIFT2);
            psum0 += sc[nt][0] + sc[nt][1];
            psum1 += sc[nt][2] + sc[nt][3];
        }

        // ---- O += Phi·Vhi ----
#pragma unroll
        for (int ktp = 0; ktp < 4; ktp++) {
            unsigned pah[4];
            pah[0] = hpack(sc[2 * ktp][0],     sc[2 * ktp][1]);
            pah[1] = hpack(sc[2 * ktp][2],     sc[2 * ktp][3]);
            pah[2] = hpack(sc[2 * ktp + 1][0], sc[2 * ktp + 1][1]);
            pah[3] = hpack(sc[2 * ktp + 1][2], sc[2 * ktp + 1][3]);
#pragma unroll
            for (int ntp = 0; ntp < 4; ntp++) {
                unsigned vHf[4];
                ldsm4(vHf, vcur + ntp * (16 * VSTR * 2) + ktp * 32);
                mma16816(oc[2 * ntp],     pah, vHf[0], vHf[1]);
                mma16816(oc[2 * ntp + 1], pah, vHf[2], vHf[3]);
            }
        }
    }
    __syncthreads();

    // ---- final rowsum reduce ----
    psum0 += __shfl_xor_sync(0xffffffffu, psum0, 1);
    psum0 += __shfl_xor_sync(0xffffffffu, psum0, 2);
    psum1 += __shfl_xor_sync(0xffffffffu, psum1, 1);
    psum1 += __shfl_xor_sync(0xffffffffu, psum1, 2);
    const float ri0 = 1.0f / psum0, ri1 = 1.0f / psum1;

    // ---- epilogue: normalize, transpose via smem, store, BN2 partials ----
    const int r0 = lane >> 2;
    const int col2 = (lane & 3) << 1;
    const int lbase = w << 4;
#pragma unroll
    for (int nt = 0; nt < 8; nt++) {
        int c = (nt << 3) + col2;
        Os[c * OSTR + lbase + r0]           = oc[nt][0] * ri0;
        Os[(c + 1) * OSTR + lbase + r0]     = oc[nt][1] * ri0;
        Os[c * OSTR + lbase + r0 + 8]       = oc[nt][2] * ri1;
        Os[(c + 1) * OSTR + lbase + r0 + 8] = oc[nt][3] * ri1;
    }
    __syncthreads();

#pragma unroll
    for (int kk = 0; kk < 8; kk++) {
        int f = t + kk * 256;
        int c = f >> 5, pos = (f & 31) << 2;
        float4 val = *(const float4*)(Os + c * OSTR + pos);
        *(float4*)(out + (((size_t)b * NCH + h * 64 + c) << 10) + l0 + pos) = val;
    }

    if (t < 64) {
        float s = 0.f, sq = 0.f;
#pragma unroll 16
        for (int l = 0; l < 128; l++) {
            float x = Os[t * OSTR + l];
            s += x; sq += x * x;
        }
        int ch   = h * 64 + t;
        int part = b * 8 + blockIdx.x;
        g_ch_sum[ch * 64 + part] = s;
        g_ch_sq [ch * 64 + part] = sq;
    }
}

// =====================================================================
// Kernel 4: fused BN2 finalize + affine + exact GELU. One CTA/channel.
// Loads batched up front (MLP=8) to break the latency chain.
// =====================================================================
__global__ void __launch_bounds__(256) bn_gelu_fused(
    const float* __restrict__ gamma_val, const float* __restrict__ beta_val,
    float* __restrict__ out)
{
    __shared__ float sb[2];
    const int ch = blockIdx.x;
    const int t = threadIdx.x, lane = t & 31, w = t >> 5;

    // batched loads first: 8 independent float4 in flight
    float4 x[NB];
#pragma unroll
    for (int b = 0; b < NB; b++)
        x[b] = ((const float4*)out)[((b * NCH + ch) << 8) + t];

    if (w == 0) {
        float s = g_ch_sum[ch * 64 + lane] + g_ch_sum[ch * 64 + lane + 32];
        float q = g_ch_sq [ch * 64 + lane] + g_ch_sq [ch * 64 + lane + 32];
#pragma unroll
        for (int off = 16; off >= 1; off >>= 1) {
            s += __shfl_xor_sync(0xffffffffu, s, off);
            q += __shfl_xor_sync(0xffffffffu, q, off);
        }
        if (lane == 0) {
            const float cnt = (float)NB * (float)LL;
            float mean = s / cnt;
            float var  = q / cnt - mean * mean;
            float sc   = gamma_val[ch] * rsqrtf(var + EPSF);
            sb[0] = sc;
            sb[1] = beta_val[ch] - mean * sc;
        }
    }
    __syncthreads();
    const float sc = sb[0], sh = sb[1];
    const float is2 = 0.70710678118654752440f;

#pragma unroll
    for (int b = 0; b < NB; b++) {
        float y0 = sc * x[b].x + sh, y1 = sc * x[b].y + sh;
        float y2 = sc * x[b].z + sh, y3 = sc * x[b].w + sh;
        x[b].x = 0.5f * y0 * (1.0f + erff(y0 * is2));
        x[b].y = 0.5f * y1 * (1.0f + erff(y1 * is2));
        x[b].z = 0.5f * y2 * (1.0f + erff(y2 * is2));
        x[b].w = 0.5f * y3 * (1.0f + erff(y3 * is2));
    }
#pragma unroll
    for (int b = 0; b < NB; b++)
        ((float4*)out)[((b * NCH + ch) << 8) + t] = x[b];
}

// =====================================================================
// launch
// =====================================================================
extern "C" void kernel_launch(void* const* d_in, const int* in_sizes, int n_in,
                              void* d_out, int out_size)
{
    const float* q         = (const float*)d_in[0];
    const float* k         = (const float*)d_in[1];
    const float* v         = (const float*)d_in[2];
    const float* gamma_sim = (const float*)d_in[3];
    // d_in[4] = beta_sim: cancels in softmax, unused.
    const float* gamma_val = (const float*)d_in[5];
    const float* beta_val  = (const float*)d_in[6];
    float* out = (float*)d_out;

    cudaFuncSetAttribute(attn_kernel,
                         cudaFuncAttributeMaxDynamicSharedMemorySize,
                         ATTN_SMEM_BYTES);

    gram_tc<<<dim3(64, 3), 256>>>(q, k, v);
    frob_reduce<<<64, 256>>>();
    attn_kernel<<<dim3(8, 64), 256, ATTN_SMEM_BYTES>>>(q, gamma_sim, out);
    bn_gelu_fused<<<NCH, 256>>>(gamma_val, beta_val, out);
}

// round 16
// speedup vs baseline: 1.0138x; 1.0138x over previous
#include <cuda_runtime.h>
#include <cuda_fp16.h>
#include <math.h>
#include <stdint.h>

#define NB   8
#define NH   8
#define DD   64
#define CC   64
#define LL   1024
#define MM   1024
#define NCH  512
#define BHN  64
#define EPSF 1e-3f

// attn smem layout (byte offsets)
#define QSTR 136
#define KSTR 72
#define VSTR 72
#define OSTR 132
#define QH_B  0
#define KH0_B 17408
#define KH1_B 26624
#define VH0_B 35840
#define VH1_B 45056
#define SCL_B 54272
#define ATTN_SMEM_BYTES 54288
#define KVSTRB 144            // KSTR*2 bytes per smem row

// gram smem
#define GSTR 72

#define LOG2E  1.4426950408889634f
#define SHIFT2 5.770780163555854f

// ---------------- scratch ----------------
__device__ float g_gram[2 * 64 * 4096];
__device__ float g_rsum[2 * 64 * 64];
__device__ float g_bh_sum[BHN];
__device__ float g_bh_sq[BHN];
__device__ float g_ch_sum[NCH * 64];
__device__ float g_ch_sq[NCH * 64];
__device__ __half g_kh[64 * 64 * 1024];   // fp16 K, [bh][d][m]
__device__ __half g_vh[64 * 64 * 1024];   // fp16 V, [bh][c][m]

// ---------------- helpers ----------------
__device__ __forceinline__ void ldsm4(unsigned r[4], unsigned addr) {
    asm volatile("ldmatrix.sync.aligned.m8n8.x4.shared.b16 {%0,%1,%2,%3}, [%4];"
        : "=r"(r[0]), "=r"(r[1]), "=r"(r[2]), "=r"(r[3]) : "r"(addr));
}
__device__ __forceinline__ void ldsm4t(unsigned r[4], unsigned addr) {
    asm volatile("ldmatrix.sync.aligned.m8n8.x4.trans.shared.b16 {%0,%1,%2,%3}, [%4];"
        : "=r"(r[0]), "=r"(r[1]), "=r"(r[2]), "=r"(r[3]) : "r"(addr));
}
// Non-volatile: pure register op — ptxas may interleave independent MMA
// chains with softmax math / LDSM issue. Data deps keep accumulation order
// bit-identical.
__device__ __forceinline__ void mma16816(float c[4], const unsigned a[4],
                                         unsigned b0, unsigned b1) {
    asm("mma.sync.aligned.m16n8k16.row.col.f32.f16.f16.f32 "
        "{%0,%1,%2,%3}, {%4,%5,%6,%7}, {%8,%9}, {%0,%1,%2,%3};"
        : "+f"(c[0]), "+f"(c[1]), "+f"(c[2]), "+f"(c[3])
        : "r"(a[0]), "r"(a[1]), "r"(a[2]), "r"(a[3]), "r"(b0), "r"(b1));
}
__device__ __forceinline__ void hstore2(__half* ph, int off, float x, float y) {
    __half2 H = __floats2half2_rn(x, y);
    *reinterpret_cast<__half2*>(ph + off) = H;
}
__device__ __forceinline__ unsigned hpack(float x, float y) {
    __half2 H = __floats2half2_rn(x, y);
    return *reinterpret_cast<unsigned*>(&H);
}
__device__ __forceinline__ void cpa16(uint32_t saddr, const void* gptr) {
    asm volatile("cp.async.cg.shared.global [%0], [%1], 16;"
                 :: "r"(saddr), "l"(gptr) : "memory");
}
#define CPA_COMMIT() asm volatile("cp.async.commit_group;" ::: "memory")
#define CPA_WAIT0()  asm volatile("cp.async.wait_group 0;" ::: "memory")

// =====================================================================
// Kernel 1: grid (64, 3).
//   y<2 : tensor-core Gram (Ghat = Xhi·Xhi^T + Xhi·(2Xlo)^T) + fp16 K export
//   y==2: V fp32->fp16 convert for bh = blockIdx.x (runs concurrently)
// =====================================================================
__global__ void __launch_bounds__(256) gram_tc(
    const float* __restrict__ Q, const float* __restrict__ K,
    const float* __restrict__ V)
{
    const int bh = blockIdx.x, qk = blockIdx.y;
    const int t = threadIdx.x;

    if (qk == 2) {   // ---- V convert slice: 16384 float4 for this bh ----
        int base = bh * 16384 + t;
#pragma unroll 8
        for (int i = 0; i < 64; i++) {
            int idx = base + i * 256;
            float4 v = ((const float4*)V)[idx];
            __half2 a = __floats2half2_rn(v.x, v.y);
            __half2 b = __floats2half2_rn(v.z, v.w);
            ((uint2*)g_vh)[idx] = make_uint2(*(unsigned*)&a, *(unsigned*)&b);
        }
        return;
    }

    __shared__ __align__(16) unsigned char gsm[34816];
    __half* XH  = (__half*)gsm;            // [64 l][GSTR] hi
    __half* XL2 = (__half*)(gsm + 9216);   // [64 l][GSTR] 2*lo
    float*  SX  = (float*)(gsm + 18432);   // [64 d][64 l] staging

    const float* X = (qk ? K : Q) + (size_t)bh * (DD * LL);
    const int lane = t & 31, w = t >> 5;
    const int wm = w >> 1, wn = w & 1;
    const uint32_t s0 = (uint32_t)__cvta_generic_to_shared(gsm);
    const int sd = t >> 4, smj = (t & 15) << 2;

#pragma unroll
    for (int kk = 0; kk < 4; kk++) {
        int d = sd + kk * 16;
        cpa16(s0 + 18432 + (d * 64 + smj) * 4, X + d * LL + smj);
    }
    CPA_COMMIT();

    const unsigned aoff = 2 * (((lane & 7) + ((lane & 16) >> 1)) * GSTR + (wm << 4) + (lane & 8));
    const unsigned boff = 2 * (((lane & 7) + (lane & 8)) * GSTR + ((lane & 16) >> 1) + wn * 32);

    float gc[4][4];
#pragma unroll
    for (int i = 0; i < 4; i++)
#pragma unroll
        for (int j = 0; j < 4; j++) gc[i][j] = 0.f;
    float rs[4] = {0.f, 0.f, 0.f, 0.f};

    for (int c = 0; c < 16; c++) {
        CPA_WAIT0();
        __syncthreads();
#pragma unroll
        for (int kk = 0; kk < 4; kk++) {
            int d = sd + kk * 16;
            float4 v = *(const float4*)(SX + d * 64 + smj);
            rs[kk] += v.x + v.y + v.z + v.w;
            if (qk) {   // export fp16 K (coalesced 8B per thread)
                __half2 h01 = __floats2half2_rn(v.x, v.y);
                __half2 h23 = __floats2half2_rn(v.z, v.w);
                uint2 pk = make_uint2(*(unsigned*)&h01, *(unsigned*)&h23);
                *(uint2*)(g_kh + ((((size_t)bh << 6) + d) << 10) + c * 64 + smj) = pk;
            }
            const float vv[4] = {v.x, v.y, v.z, v.w};
#pragma unroll
            for (int j = 0; j < 4; j++) {
                int jj = (j + (lane & 3)) & 3;
                float x = vv[jj];
                __half hi = __float2half_rn(x);
                XH [(smj + jj) * GSTR + d] = hi;
                XL2[(smj + jj) * GSTR + d] = __float2half_rn(2.0f * (x - __half2float(hi)));
            }
        }
        __syncthreads();
        if (c < 15) {
            int l1 = (c + 1) * 64;
#pragma unroll
            for (int kk = 0; kk < 4; kk++) {
                int d = sd + kk * 16;
                cpa16(s0 + 18432 + (d * 64 + smj) * 4, X + d * LL + l1 + smj);
            }
        }
        CPA_COMMIT();

#pragma unroll
        for (int kt = 0; kt < 4; kt++) {
            unsigned a[4];
            ldsm4t(a, s0 + aoff + kt * (16 * GSTR * 2));
#pragma unroll
            for (int ntp = 0; ntp < 2; ntp++) {
                unsigned bh4[4], bl4[4];
                unsigned ka = s0 + boff + kt * (16 * GSTR * 2) + ntp * 32;
                ldsm4t(bh4, ka);
                ldsm4t(bl4, ka + 9216);
                mma16816(gc[2 * ntp],     a, bh4[0], bh4[1]);
                mma16816(gc[2 * ntp],     a, bl4[0], bl4[1]);
                mma16816(gc[2 * ntp + 1], a, bh4[2], bh4[3]);
                mma16816(gc[2 * ntp + 1], a, bl4[2], bl4[3]);
            }
        }
    }

#pragma unroll
    for (int kk = 0; kk < 4; kk++) {
        float v = rs[kk];
        v += __shfl_xor_sync(0xffffffffu, v, 1);
        v += __shfl_xor_sync(0xffffffffu, v, 2);
        v += __shfl_xor_sync(0xffffffffu, v, 4);
        v += __shfl_xor_sync(0xffffffffu, v, 8);
        if ((lane & 15) == 0)
            g_rsum[(qk * 64 + bh) * 64 + sd + 16 * kk] = v;
    }

    float* gb = g_gram + (size_t)(qk * 64 + bh) * 4096;
    const int r = lane >> 2, cc = (lane & 3) << 1;
#pragma unroll
    for (int f = 0; f < 4; f++) {
        int m = wm * 16 + r;
        int n = wn * 32 + f * 8 + cc;
        gb[m * 64 + n]           = gc[f][0];
        gb[m * 64 + n + 1]       = gc[f][1];
        gb[(m + 8) * 64 + n]     = gc[f][2];
        gb[(m + 8) * 64 + n + 1] = gc[f][3];
    }
}

// =====================================================================
// Kernel 2: Frobenius dot + rowsum dot per (b,h).
// =====================================================================
__global__ void __launch_bounds__(256) frob_reduce()
{
    __shared__ float red[256];
    const int bh = blockIdx.x;
    const int t  = threadIdx.x;
    const float* gq = g_gram + (size_t)(0 * 64 + bh) * 4096;
    const float* gk = g_gram + (size_t)(1 * 64 + bh) * 4096;

    float acc = 0.f;
#pragma unroll
    for (int k = 0; k < 16; k++) {
        int p = t + k * 256;
        acc += gq[p] * gk[p];
    }
    red[t] = acc;
    __syncthreads();
    for (int s = 128; s > 0; s >>= 1) {
        if (t < s) red[t] += red[t + s];
        __syncthreads();
    }
    if (t == 0) g_bh_sq[bh] = red[0];
    __syncthreads();

    float rv = 0.f;
    if (t < 64) {
        rv = g_rsum[(0 * 64 + bh) * 64 + t] * g_rsum[(1 * 64 + bh) * 64 + t];
    }
    red[t] = rv;
    __syncthreads();
    for (int s = 128; s > 0; s >>= 1) {
        if (t < s) red[t] += red[t + s];
        __syncthreads();
    }
    if (t == 0) g_bh_sum[bh] = red[0];
}

// =====================================================================
// Kernel 3: fp16 flash attention, direct fp16 cp.async ping-pong.
// S = Qhi·Khi; P = exp2(s' - 4*log2e); O += Phi·Vhi. One sync per iter.
// grid (8 ltiles, 64 bh), 256 threads = 8 warps, BL=128, BM=64.
// =====================================================================
__global__ void __launch_bounds__(256, 2) attn_kernel(
    const float* __restrict__ Q, const float* __restrict__ gamma_sim,
    float* __restrict__ out)
{
    extern __shared__ __align__(16) unsigned char smraw[];
    __half* QH = (__half*)smraw;
    float* Os = (float*)smraw;   // epilogue reuse

    const int bh = blockIdx.y;
    const int l0 = blockIdx.x << 7;
    const int h  = bh & 7;
    const int b  = bh >> 3;
    const int t    = threadIdx.x;
    const int lane = t & 31;
    const int w    = t >> 5;

    const float*  Qb = Q + (size_t)bh * (DD * LL);
    const __half* Kb = g_kh + ((size_t)bh << 16);
    const __half* Vb = g_vh + ((size_t)bh << 16);

    const uint32_t s0 = (unsigned)__cvta_generic_to_shared(smraw);

    // cp.async chunk indices: 512 16B-chunks per tile (64 rows x 8)
    const int r0c = t >> 3,  c0c = (t & 7);
    const int r1c = r0c + 32;

    // ---- prologue: prefetch K/V tile 0 into buffer 0 ----
    cpa16(s0 + KH0_B + r0c * KVSTRB + c0c * 16, Kb + (r0c << 10) + c0c * 8);
    cpa16(s0 + KH0_B + r1c * KVSTRB + c0c * 16, Kb + (r1c << 10) + c0c * 8);
    cpa16(s0 + VH0_B + r0c * KVSTRB + c0c * 16, Vb + (r0c << 10) + c0c * 8);
    cpa16(s0 + VH0_B + r1c * KVSTRB + c0c * 16, Vb + (r1c << 10) + c0c * 8);
    CPA_COMMIT();

    // ---- per-head scale (folded log2e) from gram stats ----
    if (t == 0) {
        float s = 0.f, q = 0.f;
#pragma unroll
        for (int bb = 0; bb < NB; bb++) {
            s += g_bh_sum[bb * NH + h];
            q += g_bh_sq[bb * NH + h];
        }
        const float cnt = (float)NB * (float)LL * (float)MM;
        float mean = s / cnt;
        float var  = q / cnt - mean * mean;
        *(float*)(smraw + SCL_B) = gamma_sim[h] * rsqrtf(var + EPSF) * LOG2E;
    }
    __syncthreads();
    const float sscale = *(const float*)(smraw + SCL_B);

    // ---- Q tile load+convert (pre-scaled) ----
#pragma unroll
    for (int kk = 0; kk < 8; kk++) {
        int f = t + kk * 256;
        int d = f >> 5, pos = (f & 31) << 2;
        float4 val = *(const float4*)(Qb + d * LL + l0 + pos);
        int off = d * QSTR + pos;
        hstore2(QH, off,     val.x * sscale, val.y * sscale);
        hstore2(QH, off + 2, val.z * sscale, val.w * sscale);
    }
    __syncthreads();

    const unsigned qoff = QH_B + 2 * (((lane & 7) + ((lane & 16) >> 1)) * QSTR + (w << 4) + (lane & 8));
    const unsigned koff = 2 * (((lane & 7) + (lane & 8)) * KSTR + ((lane & 16) >> 1));
    const unsigned voff = 2 * (((lane & 7) + ((lane & 16) >> 1)) * VSTR + (lane & 8));

    // ---- hoist loop-invariant Q A-fragments ----
    unsigned aH[4][4];
#pragma unroll
    for (int kt = 0; kt < 4; kt++)
        ldsm4t(aH[kt], s0 + qoff + kt * (16 * QSTR * 2));

    float oc[8][4];
#pragma unroll
    for (int i = 0; i < 8; i++)
#pragma unroll
        for (int j = 0; j < 4; j++) oc[i][j] = 0.f;
    float psum0 = 0.f, psum1 = 0.f;

    for (int it = 0; it < 16; it++) {
        CPA_WAIT0();          // tile it landed in buf (it&1)
        __syncthreads();      // all see it; prev MMA done with other buf

        // ---- prefetch tile it+1 into the other buffer ----
        if (it < 15) {
            const int m1 = (it + 1) << 6;
            const uint32_t kb = s0 + ((it & 1) ? KH0_B : KH1_B);
            const uint32_t vb = s0 + ((it & 1) ? VH0_B : VH1_B);
            cpa16(kb + r0c * KVSTRB + c0c * 16, Kb + (r0c << 10) + m1 + c0c * 8);
            cpa16(kb + r1c * KVSTRB + c0c * 16, Kb + (r1c << 10) + m1 + c0c * 8);
            cpa16(vb + r0c * KVSTRB + c0c * 16, Vb + (r0c << 10) + m1 + c0c * 8);
            cpa16(vb + r1c * KVSTRB + c0c * 16, Vb + (r1c << 10) + m1 + c0c * 8);
        }
        CPA_COMMIT();

        const uint32_t kcur = s0 + ((it & 1) ? KH1_B : KH0_B) + koff;
        const uint32_t vcur = s0 + ((it & 1) ? VH1_B : VH0_B) + voff;

        // ---- S = Qhi·Khi ----
        float sc[8][4];
#pragma unroll
        for (int i = 0; i < 8; i++)
#pragma unroll
            for (int j = 0; j < 4; j++) sc[i][j] = 0.f;

#pragma unroll
        for (int kt = 0; kt < 4; kt++) {
#pragma unroll
            for (int ntp = 0; ntp < 4; ntp++) {
                unsigned bHf[4];
                ldsm4t(bHf, kcur + kt * (16 * KSTR * 2) + ntp * 32);
                mma16816(sc[2 * ntp],     aH[kt], bHf[0], bHf[1]);
                mma16816(sc[2 * ntp + 1], aH[kt], bHf[2], bHf[3]);
            }
        }

        // ---- shifted exp2 softmax ----
#pragma unroll
        for (int nt = 0; nt < 8; nt++) {
            sc[nt][0] = exp2f(sc[nt][0] - SHIFT2);
            sc[nt][1] = exp2f(sc[nt][1] - SHIFT2);
            sc[nt][2] = exp2f(sc[nt][2] - SHIFT2);
            sc[nt][3] = exp2f(sc[nt][3] - SHIFT2);
            psum0 += sc[nt][0] + sc[nt][1];
            psum1 += sc[nt][2] + sc[nt][3];
        }

        // ---- O += Phi·Vhi ----
#pragma unroll
        for (int ktp = 0; ktp < 4; ktp++) {
            unsigned pah[4];
            pah[0] = hpack(sc[2 * ktp][0],     sc[2 * ktp][1]);
            pah[1] = hpack(sc[2 * ktp][2],     sc[2 * ktp][3]);
            pah[2] = hpack(sc[2 * ktp + 1][0], sc[2 * ktp + 1][1]);
            pah[3] = hpack(sc[2 * ktp + 1][2], sc[2 * ktp + 1][3]);
#pragma unroll
            for (int ntp = 0; ntp < 4; ntp++) {
                unsigned vHf[4];
                ldsm4(vHf, vcur + ntp * (16 * VSTR * 2) + ktp * 32);
                mma16816(oc[2 * ntp],     pah, vHf[0], vHf[1]);
                mma16816(oc[2 * ntp + 1], pah, vHf[2], vHf[3]);
            }
        }
    }
    __syncthreads();

    // ---- final rowsum reduce ----
    psum0 += __shfl_xor_sync(0xffffffffu, psum0, 1);
    psum0 += __shfl_xor_sync(0xffffffffu, psum0, 2);
    psum1 += __shfl_xor_sync(0xffffffffu, psum1, 1);
    psum1 += __shfl_xor_sync(0xffffffffu, psum1, 2);
    const float ri0 = 1.0f / psum0, ri1 = 1.0f / psum1;

    // ---- epilogue: normalize, transpose via smem, store, BN2 partials ----
    const int r0 = lane >> 2;
    const int col2 = (lane & 3) << 1;
    const int lbase = w << 4;
#pragma unroll
    for (int nt = 0; nt < 8; nt++) {
        int c = (nt << 3) + col2;
        Os[c * OSTR + lbase + r0]           = oc[nt][0] * ri0;
        Os[(c + 1) * OSTR + lbase + r0]     = oc[nt][1] * ri0;
        Os[c * OSTR + lbase + r0 + 8]       = oc[nt][2] * ri1;
        Os[(c + 1) * OSTR + lbase + r0 + 8] = oc[nt][3] * ri1;
    }
    __syncthreads();

#pragma unroll
    for (int kk = 0; kk < 8; kk++) {
        int f = t + kk * 256;
        int c = f >> 5, pos = (f & 31) << 2;
        float4 val = *(const float4*)(Os + c * OSTR + pos);
        *(float4*)(out + (((size_t)b * NCH + h * 64 + c) << 10) + l0 + pos) = val;
    }

    if (t < 64) {
        float s = 0.f, sq = 0.f;
#pragma unroll 16
        for (int l = 0; l < 128; l++) {
            float x = Os[t * OSTR + l];
            s += x; sq += x * x;
        }
        int ch   = h * 64 + t;
        int part = b * 8 + blockIdx.x;
        g_ch_sum[ch * 64 + part] = s;
        g_ch_sq [ch * 64 + part] = sq;
    }
}

// =====================================================================
// Kernel 4: fused BN2 finalize + affine + exact GELU.
// grid 2048 = 512 channels x 4 slices; stats reduced redundantly per CTA.
// =====================================================================
__global__ void __launch_bounds__(256) bn_gelu_fused(
    const float* __restrict__ gamma_val, const float* __restrict__ beta_val,
    float* __restrict__ out)
{
    __shared__ float sb[2];
    const int ch   = blockIdx.x >> 2;
    const int part = blockIdx.x & 3;
    const int t = threadIdx.x, lane = t & 31, w = t >> 5;

    if (w == 0) {
        float s = g_ch_sum[ch * 64 + lane] + g_ch_sum[ch * 64 + lane + 32];
        float q = g_ch_sq [ch * 64 + lane] + g_ch_sq [ch * 64 + lane + 32];
#pragma unroll
        for (int off = 16; off >= 1; off >>= 1) {
            s += __shfl_xor_sync(0xffffffffu, s, off);
            q += __shfl_xor_sync(0xffffffffu, q, off);
        }
        if (lane == 0) {
            const float cnt = (float)NB * (float)LL;
            float mean = s / cnt;
            float var  = q / cnt - mean * mean;
            float sc   = gamma_val[ch] * rsqrtf(var + EPSF);
            sb[0] = sc;
            sb[1] = beta_val[ch] - mean * sc;
        }
    }
    __syncthreads();
    const float sc = sb[0], sh = sb[1];
    const float is2 = 0.70710678118654752440f;

#pragma unroll
    for (int bb = 0; bb < 2; bb++) {
        int b = part * 2 + bb;
        int i = ((b * NCH + ch) << 8) + t;   // float4 index
        float4 x = ((const float4*)out)[i];
        float y0 = sc * x.x + sh, y1 = sc * x.y + sh;
        float y2 = sc * x.z + sh, y3 = sc * x.w + sh;
        x.x = 0.5f * y0 * (1.0f + erff(y0 * is2));
        x.y = 0.5f * y1 * (1.0f + erff(y1 * is2));
        x.z = 0.5f * y2 * (1.0f + erff(y2 * is2));
        x.w = 0.5f * y3 * (1.0f + erff(y3 * is2));
        ((float4*)out)[i] = x;
    }
}

// =====================================================================
// launch
// =====================================================================
extern "C" void kernel_launch(void* const* d_in, const int* in_sizes, int n_in,
                              void* d_out, int out_size)
{
    const float* q         = (const float*)d_in[0];
    const float* k         = (const float*)d_in[1];
    const float* v         = (const float*)d_in[2];
    const float* gamma_sim = (const float*)d_in[3];
    // d_in[4] = beta_sim: cancels in softmax, unused.
    const float* gamma_val = (const float*)d_in[5];
    const float* beta_val  = (const float*)d_in[6];
    float* out = (float*)d_out;

    cudaFuncSetAttribute(attn_kernel,
                         cudaFuncAttributeMaxDynamicSharedMemorySize,
                         ATTN_SMEM_BYTES);

    gram_tc<<<dim3(64, 3), 256>>>(q, k, v);
    frob_reduce<<<64, 256>>>();
    attn_kernel<<<dim3(8, 64), 256, ATTN_SMEM_BYTES>>>(q, gamma_sim, out);
    bn_gelu_fused<<<2048, 256>>>(gamma_val, beta_val, out);
}